// round 3
// baseline (speedup 1.0000x reference)
#include <cuda_runtime.h>
#include <cuda_bf16.h>
#include <math.h>

// Problem constants
#define B_  2
#define S_  2048
#define D_  2048
#define H_  16
#define HD_ 128
#define M_  (B_ * S_)              // 4096
#define TOT_ (B_ * H_ * S_ * HD_)  // 8388608

// ---------------------------------------------------------------------------
// PTX helpers (sm_80+ portable only — NO 'a'-suffix features)
// ---------------------------------------------------------------------------
__device__ __forceinline__ unsigned smem_u32(const void* p) {
    unsigned a;
    asm("{ .reg .u64 t; cvta.to.shared.u64 t, %1; cvt.u32.u64 %0, t; }"
        : "=r"(a) : "l"(p));
    return a;
}
__device__ __forceinline__ void cp16(unsigned dst, const void* src) {
    asm volatile("cp.async.cg.shared.global [%0], [%1], 16;" :: "r"(dst), "l"(src));
}
#define CP_COMMIT() asm volatile("cp.async.commit_group;" ::: "memory")
#define CP_WAIT(n)  asm volatile("cp.async.wait_group %0;" :: "n"(n) : "memory")

__device__ __forceinline__ void ldsm4(unsigned& r0, unsigned& r1, unsigned& r2,
                                      unsigned& r3, unsigned addr) {
    asm volatile("ldmatrix.sync.aligned.m8n8.x4.shared.b16 {%0,%1,%2,%3}, [%4];"
                 : "=r"(r0), "=r"(r1), "=r"(r2), "=r"(r3) : "r"(addr));
}
__device__ __forceinline__ void mma_bf16(float* c, const unsigned* a,
                                         const unsigned* b) {
    asm volatile(
        "mma.sync.aligned.m16n8k16.row.col.f32.bf16.bf16.f32 "
        "{%0,%1,%2,%3}, {%4,%5,%6,%7}, {%8,%9}, {%0,%1,%2,%3};"
        : "+f"(c[0]), "+f"(c[1]), "+f"(c[2]), "+f"(c[3])
        : "r"(a[0]), "r"(a[1]), "r"(a[2]), "r"(a[3]), "r"(b[0]), "r"(b[1]));
}

// ---------------------------------------------------------------------------
// Scratch (no cudaMalloc allowed)
// ---------------------------------------------------------------------------
__device__ float g_qraw[(size_t)M_ * D_];
__device__ float g_kraw[(size_t)M_ * D_];
__device__ float g_vraw[(size_t)M_ * D_];
__device__ float g_Q[(size_t)TOT_];
__device__ float g_K[(size_t)TOT_];
__device__ float g_V[(size_t)TOT_];
__device__ float g_O[(size_t)TOT_];
__device__ float g_invf[64];

__device__ __nv_bfloat16 g_xh[(size_t)M_ * D_];
__device__ __nv_bfloat16 g_xl[(size_t)M_ * D_];
__device__ __nv_bfloat16 g_wqh[(size_t)D_ * D_];
__device__ __nv_bfloat16 g_wql[(size_t)D_ * D_];
__device__ __nv_bfloat16 g_wkh[(size_t)D_ * D_];
__device__ __nv_bfloat16 g_wkl[(size_t)D_ * D_];
__device__ __nv_bfloat16 g_wvh[(size_t)D_ * D_];
__device__ __nv_bfloat16 g_wvl[(size_t)D_ * D_];
__device__ __nv_bfloat16 g_woh[(size_t)D_ * D_];
__device__ __nv_bfloat16 g_wol[(size_t)D_ * D_];
__device__ __nv_bfloat16 g_oth[(size_t)M_ * D_];
__device__ __nv_bfloat16 g_otl[(size_t)M_ * D_];

// ---------------------------------------------------------------------------
// fp32 -> (bf16 hi, bf16 lo)
// ---------------------------------------------------------------------------
__global__ void conv_hilo(const float* __restrict__ src,
                          __nv_bfloat16* __restrict__ hi,
                          __nv_bfloat16* __restrict__ lo, int n4)
{
    int i = blockIdx.x * 256 + threadIdx.x;
    if (i >= n4) return;
    float4 v = ((const float4*)src)[i];
    __nv_bfloat16 h0 = __float2bfloat16(v.x);
    __nv_bfloat16 h1 = __float2bfloat16(v.y);
    __nv_bfloat16 h2 = __float2bfloat16(v.z);
    __nv_bfloat16 h3 = __float2bfloat16(v.w);
    __nv_bfloat16 l0 = __float2bfloat16(v.x - __bfloat162float(h0));
    __nv_bfloat16 l1 = __float2bfloat16(v.y - __bfloat162float(h1));
    __nv_bfloat16 l2 = __float2bfloat16(v.z - __bfloat162float(h2));
    __nv_bfloat16 l3 = __float2bfloat16(v.w - __bfloat162float(h3));
    ((__nv_bfloat162*)hi)[2 * i]     = __halves2bfloat162(h0, h1);
    ((__nv_bfloat162*)hi)[2 * i + 1] = __halves2bfloat162(h2, h3);
    ((__nv_bfloat162*)lo)[2 * i]     = __halves2bfloat162(l0, l1);
    ((__nv_bfloat162*)lo)[2 * i + 1] = __halves2bfloat162(l2, l3);
}

// ---------------------------------------------------------------------------
// bf16x3 split GEMM via mma.sync: C[M,N] = A[M,K] @ B[N,K]^T
// CTA 128x128, BK=32, 8 warps (warp tile 64x32), cp.async double buffer.
// Smem layout per stage: 4 matrices [128 rows][32 bf16], row stride 64B,
// 16B-chunk swizzle: phys_chunk = kchunk ^ ((row>>1)&3)  -> ldmatrix
// conflict-free.
// ---------------------------------------------------------------------------
#define GSTG   32768
#define OAH    0
#define OAL    8192
#define OBH    16384
#define OBL    24576
#define GSMEM  (2 * GSTG)

__device__ __forceinline__ void g_load_chunk(
    unsigned sb, int tid,
    const __nv_bfloat16* Ah, const __nv_bfloat16* Al,
    const __nv_bfloat16* Bh, const __nv_bfloat16* Bl,
    int m0, int n0, int Kdim, int c)
{
    const __nv_bfloat16* srcs[4] = {Ah, Al, Bh, Bl};
    const int r0s[4] = {m0, m0, n0, n0};
#pragma unroll
    for (int mat = 0; mat < 4; mat++) {
#pragma unroll
        for (int j = 0; j < 2; j++) {
            int ci = tid * 2 + j;          // 0..511
            int row = ci >> 2;
            int kc = ci & 3;
            int phys = kc ^ ((row >> 1) & 3);
            unsigned dst = sb + mat * 8192 + row * 64 + phys * 16;
            const __nv_bfloat16* src =
                srcs[mat] + (size_t)(r0s[mat] + row) * Kdim + c * 32 + kc * 8;
            cp16(dst, src);
        }
    }
}

__global__ void __launch_bounds__(256)
gemm_bf16x3(const __nv_bfloat16* __restrict__ Ahi, const __nv_bfloat16* __restrict__ Alo,
            const __nv_bfloat16* __restrict__ Bhi, const __nv_bfloat16* __restrict__ Blo,
            float* __restrict__ C, int Kdim, int Ndim)
{
    extern __shared__ char smem[];
    const unsigned sb = smem_u32(smem);
    const int tid = threadIdx.x;
    const int lane = tid & 31;
    const int wid = tid >> 5;
    const int wm = wid & 1;        // 2 warps along M
    const int wn = wid >> 1;       // 4 warps along N
    const int m0 = blockIdx.y * 128;
    const int n0 = blockIdx.x * 128;
    const int nch = Kdim / 32;

    float acc[4][4][4];
#pragma unroll
    for (int i = 0; i < 4; i++)
#pragma unroll
        for (int j = 0; j < 4; j++)
#pragma unroll
            for (int k = 0; k < 4; k++) acc[i][j][k] = 0.f;

    // ldmatrix lane row/chunk pattern (within a 16x16 b16 region)
    const int lrow = (lane & 7) + ((lane >> 3) & 1) * 8;  // 0..15
    const int lchv = (lane >> 4);                          // 0 or 1 (k-chunk)

    g_load_chunk(sb, tid, Ahi, Alo, Bhi, Blo, m0, n0, Kdim, 0);
    CP_COMMIT();

    for (int c = 0; c < nch; c++) {
        const unsigned sbc = sb + (c & 1) * GSTG;
        if (c + 1 < nch) {
            g_load_chunk(sb + ((c + 1) & 1) * GSTG, tid, Ahi, Alo, Bhi, Blo,
                         m0, n0, Kdim, c + 1);
            CP_COMMIT();
            CP_WAIT(1);
        } else {
            CP_WAIT(0);
        }
        __syncthreads();

#pragma unroll
        for (int s = 0; s < 2; s++) {          // two k16 steps per chunk
            unsigned ah[4][4], al[4][4], bh[4][2], bl[4][2];
            // A frags: 4 m-tiles, hi & lo
#pragma unroll
            for (int mt = 0; mt < 4; mt++) {
                int row = wm * 64 + mt * 16 + lrow;
                int ch = 2 * s + lchv;
                int phys = ch ^ ((row >> 1) & 3);
                unsigned addr = sbc + row * 64 + phys * 16;
                ldsm4(ah[mt][0], ah[mt][1], ah[mt][2], ah[mt][3], addr + OAH);
                ldsm4(al[mt][0], al[mt][1], al[mt][2], al[mt][3], addr + OAL);
            }
            // B frags: 2 ldmatrix.x4 cover 4 n-tiles (each gives 2 tiles)
#pragma unroll
            for (int p = 0; p < 2; p++) {
                int row = wn * 32 + p * 16 + lrow;
                int ch = 2 * s + lchv;
                int phys = ch ^ ((row >> 1) & 3);
                unsigned addr = sbc + row * 64 + phys * 16;
                unsigned r0, r1, r2, r3;
                ldsm4(r0, r1, r2, r3, addr + OBH);
                bh[2 * p][0] = r0; bh[2 * p + 1][0] = r1;
                bh[2 * p][1] = r2; bh[2 * p + 1][1] = r3;
                ldsm4(r0, r1, r2, r3, addr + OBL);
                bl[2 * p][0] = r0; bl[2 * p + 1][0] = r1;
                bl[2 * p][1] = r2; bl[2 * p + 1][1] = r3;
            }
            // 3 passes: hh, hl, lh
#pragma unroll
            for (int mt = 0; mt < 4; mt++)
#pragma unroll
                for (int nt = 0; nt < 4; nt++)
                    mma_bf16(acc[mt][nt], ah[mt], bh[nt]);
#pragma unroll
            for (int mt = 0; mt < 4; mt++)
#pragma unroll
                for (int nt = 0; nt < 4; nt++)
                    mma_bf16(acc[mt][nt], ah[mt], bl[nt]);
#pragma unroll
            for (int mt = 0; mt < 4; mt++)
#pragma unroll
                for (int nt = 0; nt < 4; nt++)
                    mma_bf16(acc[mt][nt], al[mt], bh[nt]);
        }
        __syncthreads();
    }

    // Epilogue
    const int rbase = m0 + wm * 64 + (lane >> 2);
    const int cbase = n0 + wn * 32 + (lane & 3) * 2;
#pragma unroll
    for (int mt = 0; mt < 4; mt++) {
#pragma unroll
        for (int nt = 0; nt < 4; nt++) {
            size_t r0 = (size_t)(rbase + mt * 16) * Ndim + cbase + nt * 8;
            size_t r1 = r0 + 8 * Ndim;
            *(float2*)&C[r0] = make_float2(acc[mt][nt][0], acc[mt][nt][1]);
            *(float2*)&C[r1] = make_float2(acc[mt][nt][2], acc[mt][nt][3]);
        }
    }
}

// ---------------------------------------------------------------------------
// RoPE table (fp64 accuracy)
// ---------------------------------------------------------------------------
__global__ void init_rope()
{
    int j = threadIdx.x;
    if (j < 64) g_invf[j] = (float)exp(-(double)j * 0.14391156831212788);
}

// ---------------------------------------------------------------------------
// RoPE + pack [B,S,H*hd] -> [B,H,S,hd]
// ---------------------------------------------------------------------------
__global__ void rope_pack(const float* __restrict__ qraw,
                          const float* __restrict__ kraw,
                          const float* __restrict__ vraw,
                          float* __restrict__ Q, float* __restrict__ K,
                          float* __restrict__ V)
{
    int i = blockIdx.x * 256 + threadIdx.x;
    if (i >= TOT_) return;
    int d = i & (HD_ - 1);
    int s = (i >> 7) & (S_ - 1);
    int h = (i >> 18) & (H_ - 1);
    int b = i >> 22;

    size_t raw = (size_t)(b * S_ + s) * D_ + h * HD_ + d;
    int dp = (d < 64) ? d + 64 : d - 64;
    size_t rawp = raw + (dp - d);

    float inv = g_invf[d & 63];
    float ang = (float)s * inv;
    float sn, cs;
    sincosf(ang, &sn, &cs);

    float qv = qraw[raw], qp = qraw[rawp];
    float kv = kraw[raw], kp = kraw[rawp];
    float rq = (d < 64) ? -qp : qp;
    float rk = (d < 64) ? -kp : kp;

    Q[i] = fmaf(rq, sn, qv * cs);
    K[i] = fmaf(rk, sn, kv * cs);
    V[i] = vraw[raw];
}

// ---------------------------------------------------------------------------
// Flash attention, fp32, causal (unchanged from round 1)
// ---------------------------------------------------------------------------
struct SmemAttn {
    float Qs[128][68];
    float Ks[128][68];
    float Vs[64][128];
    float Ss[64][68];
    float mrow[64];
    float lrow[64];
    float corr[64];
};

__global__ void __launch_bounds__(256)
flash_attn(const float* __restrict__ Qg, const float* __restrict__ Kg,
           const float* __restrict__ Vg, float* __restrict__ Og)
{
    extern __shared__ char smem_raw[];
    SmemAttn& sm = *reinterpret_cast<SmemAttn*>(smem_raw);

    const int tid = threadIdx.x;
    const int tx = tid & 15;
    const int ty = tid >> 4;
    const int bh = blockIdx.y;
    const int q0 = (gridDim.x - 1 - blockIdx.x) * 64;

    const float* Qb = Qg + (size_t)bh * S_ * HD_;
    const float* Kb = Kg + (size_t)bh * S_ * HD_;
    const float* Vb = Vg + (size_t)bh * S_ * HD_;
    float* Ob       = Og + (size_t)bh * S_ * HD_;

    const float scale = 0.08838834764831845f;

    for (int i = tid; i < 64 * 32; i += 256) {
        int r = i >> 5;
        int c4 = (i & 31) * 4;
        float4 v = *(const float4*)&Qb[(size_t)(q0 + r) * HD_ + c4];
        sm.Qs[c4 + 0][r] = v.x * scale;
        sm.Qs[c4 + 1][r] = v.y * scale;
        sm.Qs[c4 + 2][r] = v.z * scale;
        sm.Qs[c4 + 3][r] = v.w * scale;
    }
    if (tid < 64) {
        sm.mrow[tid] = -1e30f;
        sm.lrow[tid] = 0.f;
    }

    float o[4][8];
#pragma unroll
    for (int i = 0; i < 4; i++)
#pragma unroll
        for (int j = 0; j < 8; j++) o[i][j] = 0.f;

    const int ntiles = q0 / 64 + 1;
    for (int kt = 0; kt < ntiles; kt++) {
        const int k0 = kt * 64;

        for (int i = tid; i < 64 * 32; i += 256) {
            int c = i >> 5;
            int c4 = (i & 31) * 4;
            float4 kv4 = *(const float4*)&Kb[(size_t)(k0 + c) * HD_ + c4];
            sm.Ks[c4 + 0][c] = kv4.x;
            sm.Ks[c4 + 1][c] = kv4.y;
            sm.Ks[c4 + 2][c] = kv4.z;
            sm.Ks[c4 + 3][c] = kv4.w;
            float4 vv4 = *(const float4*)&Vb[(size_t)(k0 + c) * HD_ + c4];
            *(float4*)&sm.Vs[c][c4] = vv4;
        }
        __syncthreads();

        float sc[4][4];
#pragma unroll
        for (int i = 0; i < 4; i++)
#pragma unroll
            for (int j = 0; j < 4; j++) sc[i][j] = 0.f;

#pragma unroll 8
        for (int k = 0; k < 128; k++) {
            float4 qa = *(const float4*)&sm.Qs[k][ty * 4];
            float4 kb = *(const float4*)&sm.Ks[k][tx * 4];
            float qq[4] = {qa.x, qa.y, qa.z, qa.w};
            float kk2[4] = {kb.x, kb.y, kb.z, kb.w};
#pragma unroll
            for (int i = 0; i < 4; i++)
#pragma unroll
                for (int j = 0; j < 4; j++)
                    sc[i][j] = fmaf(qq[i], kk2[j], sc[i][j]);
        }
#pragma unroll
        for (int i = 0; i < 4; i++) {
            int gq = q0 + ty * 4 + i;
#pragma unroll
            for (int j = 0; j < 4; j++) {
                int gk = k0 + tx * 4 + j;
                sm.Ss[ty * 4 + i][tx * 4 + j] = (gk <= gq) ? sc[i][j] : -1e30f;
            }
        }
        __syncthreads();

        {
            int r = tid >> 2;
            int q = tid & 3;
            float mx = -1e30f;
#pragma unroll
            for (int cc = 0; cc < 16; cc++)
                mx = fmaxf(mx, sm.Ss[r][q * 16 + cc]);
            mx = fmaxf(mx, __shfl_xor_sync(0xffffffffu, mx, 1));
            mx = fmaxf(mx, __shfl_xor_sync(0xffffffffu, mx, 2));
            float m_old = sm.mrow[r];
            float m_new = fmaxf(m_old, mx);
            float ssum = 0.f;
#pragma unroll
            for (int cc = 0; cc < 16; cc++) {
                float p = __expf(sm.Ss[r][q * 16 + cc] - m_new);
                sm.Ss[r][q * 16 + cc] = p;
                ssum += p;
            }
            ssum += __shfl_xor_sync(0xffffffffu, ssum, 1);
            ssum += __shfl_xor_sync(0xffffffffu, ssum, 2);
            if (q == 0) {
                float cr = __expf(m_old - m_new);
                sm.lrow[r] = sm.lrow[r] * cr + ssum;
                sm.mrow[r] = m_new;
                sm.corr[r] = cr;
            }
        }
        __syncthreads();

#pragma unroll
        for (int i = 0; i < 4; i++) {
            float cr = sm.corr[ty * 4 + i];
#pragma unroll
            for (int j = 0; j < 8; j++) o[i][j] *= cr;
        }
#pragma unroll 4
        for (int c = 0; c < 64; c++) {
            float4 v0 = *(const float4*)&sm.Vs[c][tx * 8];
            float4 v1 = *(const float4*)&sm.Vs[c][tx * 8 + 4];
            float vv[8] = {v0.x, v0.y, v0.z, v0.w, v1.x, v1.y, v1.z, v1.w};
#pragma unroll
            for (int i = 0; i < 4; i++) {
                float p = sm.Ss[ty * 4 + i][c];
#pragma unroll
                for (int j = 0; j < 8; j++)
                    o[i][j] = fmaf(p, vv[j], o[i][j]);
            }
        }
        __syncthreads();
    }

#pragma unroll
    for (int i = 0; i < 4; i++) {
        float invl = 1.f / sm.lrow[ty * 4 + i];
        size_t off = (size_t)(q0 + ty * 4 + i) * HD_ + tx * 8;
        float4 w0 = make_float4(o[i][0] * invl, o[i][1] * invl,
                                o[i][2] * invl, o[i][3] * invl);
        float4 w1 = make_float4(o[i][4] * invl, o[i][5] * invl,
                                o[i][6] * invl, o[i][7] * invl);
        *(float4*)&Ob[off] = w0;
        *(float4*)&Ob[off + 4] = w1;
    }
}

// ---------------------------------------------------------------------------
// O [B,H,S,hd] -> Ot [B*S, D] fused with bf16 hi/lo split
// ---------------------------------------------------------------------------
__global__ void transpose_conv(const float* __restrict__ O,
                               __nv_bfloat16* __restrict__ hi,
                               __nv_bfloat16* __restrict__ lo)
{
    int i = blockIdx.x * 256 + threadIdx.x;
    if (i >= TOT_) return;
    int n = i & (D_ - 1);
    int m = i >> 11;
    int d = n & (HD_ - 1);
    int h = n >> 7;
    int s = m & (S_ - 1);
    int b = m >> 11;
    float v = O[(((size_t)(b * H_ + h) * S_ + s) << 7) + d];
    __nv_bfloat16 hv = __float2bfloat16(v);
    hi[i] = hv;
    lo[i] = __float2bfloat16(v - __bfloat162float(hv));
}

// ---------------------------------------------------------------------------
// Launch
// ---------------------------------------------------------------------------
extern "C" void kernel_launch(void* const* d_in, const int* in_sizes, int n_in,
                              void* d_out, int out_size)
{
    const float* x  = (const float*)d_in[0];
    const float* Wq = (const float*)d_in[1];
    const float* Wk = (const float*)d_in[2];
    const float* Wv = (const float*)d_in[3];
    const float* Wo = (const float*)d_in[4];
    float* out = (float*)d_out;
    (void)in_sizes; (void)n_in; (void)out_size;

    cudaFuncSetAttribute(gemm_bf16x3, cudaFuncAttributeMaxDynamicSharedMemorySize, GSMEM);
    cudaFuncSetAttribute(flash_attn, cudaFuncAttributeMaxDynamicSharedMemorySize,
                         (int)sizeof(SmemAttn));

    init_rope<<<1, 64>>>();

    const int nx4 = (M_ * D_) / 4;
    const int nw4 = (D_ * D_) / 4;
    conv_hilo<<<(nx4 + 255) / 256, 256>>>(x,  g_xh,  g_xl,  nx4);
    conv_hilo<<<(nw4 + 255) / 256, 256>>>(Wq, g_wqh, g_wql, nw4);
    conv_hilo<<<(nw4 + 255) / 256, 256>>>(Wk, g_wkh, g_wkl, nw4);
    conv_hilo<<<(nw4 + 255) / 256, 256>>>(Wv, g_wvh, g_wvl, nw4);
    conv_hilo<<<(nw4 + 255) / 256, 256>>>(Wo, g_woh, g_wol, nw4);

    dim3 gg(D_ / 128, M_ / 128);   // (16, 32)
    gemm_bf16x3<<<gg, 256, GSMEM>>>(g_xh, g_xl, g_wqh, g_wql, g_qraw, D_, D_);
    gemm_bf16x3<<<gg, 256, GSMEM>>>(g_xh, g_xl, g_wkh, g_wkl, g_kraw, D_, D_);
    gemm_bf16x3<<<gg, 256, GSMEM>>>(g_xh, g_xl, g_wvh, g_wvl, g_vraw, D_, D_);

    rope_pack<<<TOT_ / 256, 256>>>(g_qraw, g_kraw, g_vraw, g_Q, g_K, g_V);

    flash_attn<<<dim3(S_ / 64, B_ * H_), 256, sizeof(SmemAttn)>>>(g_Q, g_K, g_V, g_O);

    transpose_conv<<<TOT_ / 256, 256>>>(g_O, g_oth, g_otl);

    gemm_bf16x3<<<gg, 256, GSMEM>>>(g_oth, g_otl, g_woh, g_wol, out, D_, D_);
}

// round 4
// speedup vs baseline: 4.7887x; 4.7887x over previous
#include <cuda_runtime.h>
#include <cuda_bf16.h>
#include <math.h>

// Problem constants
#define B_  2
#define S_  2048
#define D_  2048
#define H_  16
#define HD_ 128
#define M_  (B_ * S_)              // 4096
#define TOT_ (B_ * H_ * S_ * HD_)  // 8388608

typedef unsigned long long u64;

// ---------------------------------------------------------------------------
// f32x2 packed-math helpers (PTX sm_100+ family feature, non-'a')
// ---------------------------------------------------------------------------
__device__ __forceinline__ void ffma2(u64& d, u64 a, u64 b) {
    asm("fma.rn.f32x2 %0, %1, %2, %0;" : "+l"(d) : "l"(a), "l"(b));
}
__device__ __forceinline__ void fmul2(u64& d, u64 a) {
    asm("mul.rn.f32x2 %0, %0, %1;" : "+l"(d) : "l"(a));
}
__device__ __forceinline__ u64 pk2(float x, float y) {
    u64 r;
    asm("mov.b64 %0, {%1, %2};" : "=l"(r) : "f"(x), "f"(y));
    return r;
}
__device__ __forceinline__ void upk2(u64 v, float& x, float& y) {
    asm("mov.b64 {%0, %1}, %2;" : "=f"(x), "=f"(y) : "l"(v));
}

// ---------------------------------------------------------------------------
// Scratch (no cudaMalloc allowed)
// ---------------------------------------------------------------------------
__device__ float g_qraw[(size_t)M_ * D_];
__device__ float g_kraw[(size_t)M_ * D_];
__device__ float g_vraw[(size_t)M_ * D_];
__device__ float g_Q[(size_t)TOT_];
__device__ float g_K[(size_t)TOT_];
__device__ float g_V[(size_t)TOT_];
__device__ float g_O[(size_t)TOT_];
__device__ float g_Ot[(size_t)M_ * D_];
__device__ float g_invf[64];

// ---------------------------------------------------------------------------
// SGEMM (FFMA2): C[M,N] = A[M,K] @ B[N,K]^T, row-major.
// 128x128 tile, BK=16, 256 threads, 8x8/thread as 8x4 f32x2 pairs.
// Register prefetch + smem double buffer: one __syncthreads per k-tile.
// ---------------------------------------------------------------------------
#define BM 128
#define BN 128
#define BK 16

__global__ void __launch_bounds__(256)
gemm_f2(const float* __restrict__ A, const float* __restrict__ Bw,
        float* __restrict__ C, int Mdim, int Ndim, int Kdim)
{
    __shared__ float As[2][BK][BM + 4];
    __shared__ float Bs[2][BK][BN + 4];

    const int tid = threadIdx.x;
    const int tx = tid & 15;
    const int ty = tid >> 4;
    const int m0 = blockIdx.y * BM;
    const int n0 = blockIdx.x * BN;

    const int row = (tid * 2) >> 2;          // slot it=0
    const int c4a = ((tid * 2) & 3) * 4;
    const int row2 = (tid * 2 + 1) >> 2;     // slot it=1
    const int c4b = ((tid * 2 + 1) & 3) * 4;

    float4 pa0, pa1, pb0, pb1;
    // prefetch tile 0
    pa0 = *(const float4*)&A[(size_t)(m0 + row) * Kdim + c4a];
    pa1 = *(const float4*)&A[(size_t)(m0 + row2) * Kdim + c4b];
    pb0 = *(const float4*)&Bw[(size_t)(n0 + row) * Kdim + c4a];
    pb1 = *(const float4*)&Bw[(size_t)(n0 + row2) * Kdim + c4b];

    // store tile 0 into buffer 0 (transposed)
    As[0][c4a + 0][row] = pa0.x; As[0][c4a + 1][row] = pa0.y;
    As[0][c4a + 2][row] = pa0.z; As[0][c4a + 3][row] = pa0.w;
    As[0][c4b + 0][row2] = pa1.x; As[0][c4b + 1][row2] = pa1.y;
    As[0][c4b + 2][row2] = pa1.z; As[0][c4b + 3][row2] = pa1.w;
    Bs[0][c4a + 0][row] = pb0.x; Bs[0][c4a + 1][row] = pb0.y;
    Bs[0][c4a + 2][row] = pb0.z; Bs[0][c4a + 3][row] = pb0.w;
    Bs[0][c4b + 0][row2] = pb1.x; Bs[0][c4b + 1][row2] = pb1.y;
    Bs[0][c4b + 2][row2] = pb1.z; Bs[0][c4b + 3][row2] = pb1.w;
    __syncthreads();

    u64 acc2[8][4];
#pragma unroll
    for (int i = 0; i < 8; i++)
#pragma unroll
        for (int j = 0; j < 4; j++) acc2[i][j] = 0ull;

    const int nt = Kdim / BK;
    for (int t = 0; t < nt; t++) {
        const int buf = t & 1;
        if (t + 1 < nt) {
            const int ko = (t + 1) * BK;
            pa0 = *(const float4*)&A[(size_t)(m0 + row) * Kdim + ko + c4a];
            pa1 = *(const float4*)&A[(size_t)(m0 + row2) * Kdim + ko + c4b];
            pb0 = *(const float4*)&Bw[(size_t)(n0 + row) * Kdim + ko + c4a];
            pb1 = *(const float4*)&Bw[(size_t)(n0 + row2) * Kdim + ko + c4b];
        }

#pragma unroll
        for (int kk = 0; kk < BK; kk++) {
            float4 a0 = *(const float4*)&As[buf][kk][ty * 8];
            float4 a1 = *(const float4*)&As[buf][kk][ty * 8 + 4];
            ulonglong2 bp0 = *(const ulonglong2*)&Bs[buf][kk][tx * 8];
            ulonglong2 bp1 = *(const ulonglong2*)&Bs[buf][kk][tx * 8 + 4];
            u64 bp[4] = {bp0.x, bp0.y, bp1.x, bp1.y};
            u64 ad[8];
            ad[0] = pk2(a0.x, a0.x); ad[1] = pk2(a0.y, a0.y);
            ad[2] = pk2(a0.z, a0.z); ad[3] = pk2(a0.w, a0.w);
            ad[4] = pk2(a1.x, a1.x); ad[5] = pk2(a1.y, a1.y);
            ad[6] = pk2(a1.z, a1.z); ad[7] = pk2(a1.w, a1.w);
#pragma unroll
            for (int i = 0; i < 8; i++)
#pragma unroll
                for (int j = 0; j < 4; j++)
                    ffma2(acc2[i][j], ad[i], bp[j]);
        }

        if (t + 1 < nt) {
            const int nb = (t + 1) & 1;
            As[nb][c4a + 0][row] = pa0.x; As[nb][c4a + 1][row] = pa0.y;
            As[nb][c4a + 2][row] = pa0.z; As[nb][c4a + 3][row] = pa0.w;
            As[nb][c4b + 0][row2] = pa1.x; As[nb][c4b + 1][row2] = pa1.y;
            As[nb][c4b + 2][row2] = pa1.z; As[nb][c4b + 3][row2] = pa1.w;
            Bs[nb][c4a + 0][row] = pb0.x; Bs[nb][c4a + 1][row] = pb0.y;
            Bs[nb][c4a + 2][row] = pb0.z; Bs[nb][c4a + 3][row] = pb0.w;
            Bs[nb][c4b + 0][row2] = pb1.x; Bs[nb][c4b + 1][row2] = pb1.y;
            Bs[nb][c4b + 2][row2] = pb1.z; Bs[nb][c4b + 3][row2] = pb1.w;
            __syncthreads();
        }
    }

#pragma unroll
    for (int i = 0; i < 8; i++) {
        float c0, c1, c2, c3, c4, c5, c6, c7;
        upk2(acc2[i][0], c0, c1); upk2(acc2[i][1], c2, c3);
        upk2(acc2[i][2], c4, c5); upk2(acc2[i][3], c6, c7);
        size_t r = (size_t)(m0 + ty * 8 + i) * Ndim + n0 + tx * 8;
        *(float4*)&C[r]     = make_float4(c0, c1, c2, c3);
        *(float4*)&C[r + 4] = make_float4(c4, c5, c6, c7);
    }
}

// ---------------------------------------------------------------------------
// RoPE table (fp64 accuracy, tiny)
// ---------------------------------------------------------------------------
__global__ void init_rope()
{
    int j = threadIdx.x;
    if (j < 64) g_invf[j] = (float)exp(-(double)j * 0.14391156831212788);
}

// ---------------------------------------------------------------------------
// RoPE + pack [B,S,H*hd] -> [B,H,S,hd]
// ---------------------------------------------------------------------------
__global__ void rope_pack(const float* __restrict__ qraw,
                          const float* __restrict__ kraw,
                          const float* __restrict__ vraw,
                          float* __restrict__ Q, float* __restrict__ K,
                          float* __restrict__ V)
{
    int i = blockIdx.x * 256 + threadIdx.x;
    if (i >= TOT_) return;
    int d = i & (HD_ - 1);
    int s = (i >> 7) & (S_ - 1);
    int h = (i >> 18) & (H_ - 1);
    int b = i >> 22;

    size_t raw = (size_t)(b * S_ + s) * D_ + h * HD_ + d;
    int dp = (d < 64) ? d + 64 : d - 64;
    size_t rawp = raw + (dp - d);

    float inv = g_invf[d & 63];
    float ang = (float)s * inv;
    float sn, cs;
    sincosf(ang, &sn, &cs);

    float qv = qraw[raw], qp = qraw[rawp];
    float kv = kraw[raw], kp = kraw[rawp];
    float rq = (d < 64) ? -qp : qp;
    float rk = (d < 64) ? -kp : kp;

    Q[i] = fmaf(rq, sn, qv * cs);
    K[i] = fmaf(rk, sn, kv * cs);
    V[i] = vraw[raw];
}

// ---------------------------------------------------------------------------
// Flash attention, fp32 + FFMA2 inner loops, causal.
// One block = one (b*h, 64-row q tile).
// ---------------------------------------------------------------------------
struct SmemAttn {
    float Qs[128][68];   // [k][r], Q^T, scaled
    float Ks[128][68];   // [k][c], K^T
    float Vs[64][128];   // [c][d]
    float Ss[64][68];    // scores / probs
    float mrow[64];
    float lrow[64];
    float corr[64];
};

__global__ void __launch_bounds__(256)
flash_attn(const float* __restrict__ Qg, const float* __restrict__ Kg,
           const float* __restrict__ Vg, float* __restrict__ Og)
{
    extern __shared__ char smem_raw[];
    SmemAttn& sm = *reinterpret_cast<SmemAttn*>(smem_raw);

    const int tid = threadIdx.x;
    const int tx = tid & 15;
    const int ty = tid >> 4;
    const int bh = blockIdx.y;
    const int q0 = (gridDim.x - 1 - blockIdx.x) * 64;   // heavy tiles first

    const float* Qb = Qg + (size_t)bh * S_ * HD_;
    const float* Kb = Kg + (size_t)bh * S_ * HD_;
    const float* Vb = Vg + (size_t)bh * S_ * HD_;
    float* Ob       = Og + (size_t)bh * S_ * HD_;

    const float scale = 0.08838834764831845f; // 128^-0.5

    for (int i = tid; i < 64 * 32; i += 256) {
        int r = i >> 5;
        int c4 = (i & 31) * 4;
        float4 v = *(const float4*)&Qb[(size_t)(q0 + r) * HD_ + c4];
        sm.Qs[c4 + 0][r] = v.x * scale;
        sm.Qs[c4 + 1][r] = v.y * scale;
        sm.Qs[c4 + 2][r] = v.z * scale;
        sm.Qs[c4 + 3][r] = v.w * scale;
    }
    if (tid < 64) {
        sm.mrow[tid] = -1e30f;
        sm.lrow[tid] = 0.f;
    }

    u64 o2[4][4];
#pragma unroll
    for (int i = 0; i < 4; i++)
#pragma unroll
        for (int j = 0; j < 4; j++) o2[i][j] = 0ull;

    const int ntiles = q0 / 64 + 1;
    for (int kt = 0; kt < ntiles; kt++) {
        const int k0 = kt * 64;

        for (int i = tid; i < 64 * 32; i += 256) {
            int c = i >> 5;
            int c4 = (i & 31) * 4;
            float4 kv4 = *(const float4*)&Kb[(size_t)(k0 + c) * HD_ + c4];
            sm.Ks[c4 + 0][c] = kv4.x;
            sm.Ks[c4 + 1][c] = kv4.y;
            sm.Ks[c4 + 2][c] = kv4.z;
            sm.Ks[c4 + 3][c] = kv4.w;
            float4 vv4 = *(const float4*)&Vb[(size_t)(k0 + c) * HD_ + c4];
            *(float4*)&sm.Vs[c][c4] = vv4;
        }
        __syncthreads();

        // Scores: 4 rows x 4 cols per thread = 4x2 f32x2 pairs
        u64 sc2[4][2];
#pragma unroll
        for (int i = 0; i < 4; i++) { sc2[i][0] = 0ull; sc2[i][1] = 0ull; }

#pragma unroll 4
        for (int k = 0; k < 128; k++) {
            float4 qa = *(const float4*)&sm.Qs[k][ty * 4];
            ulonglong2 kp = *(const ulonglong2*)&sm.Ks[k][tx * 4];
            u64 qd[4];
            qd[0] = pk2(qa.x, qa.x); qd[1] = pk2(qa.y, qa.y);
            qd[2] = pk2(qa.z, qa.z); qd[3] = pk2(qa.w, qa.w);
#pragma unroll
            for (int i = 0; i < 4; i++) {
                ffma2(sc2[i][0], qd[i], kp.x);
                ffma2(sc2[i][1], qd[i], kp.y);
            }
        }
        // causal mask + store
#pragma unroll
        for (int i = 0; i < 4; i++) {
            int gq = q0 + ty * 4 + i;
            float s0, s1, s2, s3;
            upk2(sc2[i][0], s0, s1);
            upk2(sc2[i][1], s2, s3);
            int gk = k0 + tx * 4;
            sm.Ss[ty * 4 + i][tx * 4 + 0] = (gk + 0 <= gq) ? s0 : -1e30f;
            sm.Ss[ty * 4 + i][tx * 4 + 1] = (gk + 1 <= gq) ? s1 : -1e30f;
            sm.Ss[ty * 4 + i][tx * 4 + 2] = (gk + 2 <= gq) ? s2 : -1e30f;
            sm.Ss[ty * 4 + i][tx * 4 + 3] = (gk + 3 <= gq) ? s3 : -1e30f;
        }
        __syncthreads();

        // Online softmax: 4 threads per row, 16 cols each
        {
            int r = tid >> 2;
            int q = tid & 3;
            float mx = -1e30f;
#pragma unroll
            for (int cc = 0; cc < 16; cc++)
                mx = fmaxf(mx, sm.Ss[r][q * 16 + cc]);
            mx = fmaxf(mx, __shfl_xor_sync(0xffffffffu, mx, 1));
            mx = fmaxf(mx, __shfl_xor_sync(0xffffffffu, mx, 2));
            float m_old = sm.mrow[r];
            float m_new = fmaxf(m_old, mx);
            float ssum = 0.f;
#pragma unroll
            for (int cc = 0; cc < 16; cc++) {
                float p = __expf(sm.Ss[r][q * 16 + cc] - m_new);
                sm.Ss[r][q * 16 + cc] = p;
                ssum += p;
            }
            ssum += __shfl_xor_sync(0xffffffffu, ssum, 1);
            ssum += __shfl_xor_sync(0xffffffffu, ssum, 2);
            if (q == 0) {
                float cr = __expf(m_old - m_new);
                sm.lrow[r] = sm.lrow[r] * cr + ssum;
                sm.mrow[r] = m_new;
                sm.corr[r] = cr;
            }
        }
        __syncthreads();

        // O update: rows ty*4+i, cols tx*8..+7 as 4 f32x2 pairs
#pragma unroll
        for (int i = 0; i < 4; i++) {
            float cr = sm.corr[ty * 4 + i];
            u64 crd = pk2(cr, cr);
#pragma unroll
            for (int j = 0; j < 4; j++) fmul2(o2[i][j], crd);
        }
#pragma unroll 4
        for (int c = 0; c < 64; c++) {
            ulonglong2 v0 = *(const ulonglong2*)&sm.Vs[c][tx * 8];
            ulonglong2 v1 = *(const ulonglong2*)&sm.Vs[c][tx * 8 + 4];
            u64 vp[4] = {v0.x, v0.y, v1.x, v1.y};
#pragma unroll
            for (int i = 0; i < 4; i++) {
                float p = sm.Ss[ty * 4 + i][c];
                u64 pd = pk2(p, p);
#pragma unroll
                for (int j = 0; j < 4; j++)
                    ffma2(o2[i][j], pd, vp[j]);
            }
        }
        __syncthreads();
    }

    // Normalize and write out
#pragma unroll
    for (int i = 0; i < 4; i++) {
        float invl = 1.f / sm.lrow[ty * 4 + i];
        float f[8];
        upk2(o2[i][0], f[0], f[1]); upk2(o2[i][1], f[2], f[3]);
        upk2(o2[i][2], f[4], f[5]); upk2(o2[i][3], f[6], f[7]);
        size_t off = (size_t)(q0 + ty * 4 + i) * HD_ + tx * 8;
        *(float4*)&Ob[off]     = make_float4(f[0] * invl, f[1] * invl,
                                             f[2] * invl, f[3] * invl);
        *(float4*)&Ob[off + 4] = make_float4(f[4] * invl, f[5] * invl,
                                             f[6] * invl, f[7] * invl);
    }
}

// ---------------------------------------------------------------------------
// O [B,H,S,hd] -> Ot [B*S, D]
// ---------------------------------------------------------------------------
__global__ void transpose_O(const float* __restrict__ O, float* __restrict__ Ot)
{
    int i = blockIdx.x * 256 + threadIdx.x;
    if (i >= TOT_) return;
    int n = i & (D_ - 1);
    int m = i >> 11;
    int d = n & (HD_ - 1);
    int h = n >> 7;
    int s = m & (S_ - 1);
    int b = m >> 11;
    Ot[i] = O[(((size_t)(b * H_ + h) * S_ + s) << 7) + d];
}

// ---------------------------------------------------------------------------
// Launch
// ---------------------------------------------------------------------------
extern "C" void kernel_launch(void* const* d_in, const int* in_sizes, int n_in,
                              void* d_out, int out_size)
{
    const float* x  = (const float*)d_in[0];
    const float* Wq = (const float*)d_in[1];
    const float* Wk = (const float*)d_in[2];
    const float* Wv = (const float*)d_in[3];
    const float* Wo = (const float*)d_in[4];
    float* out = (float*)d_out;
    (void)in_sizes; (void)n_in; (void)out_size;

    cudaFuncSetAttribute(flash_attn, cudaFuncAttributeMaxDynamicSharedMemorySize,
                         (int)sizeof(SmemAttn));

    init_rope<<<1, 64>>>();

    dim3 gg(D_ / BN, M_ / BM);   // (16, 32)
    gemm_f2<<<gg, 256>>>(x, Wq, g_qraw, M_, D_, D_);
    gemm_f2<<<gg, 256>>>(x, Wk, g_kraw, M_, D_, D_);
    gemm_f2<<<gg, 256>>>(x, Wv, g_vraw, M_, D_, D_);

    rope_pack<<<TOT_ / 256, 256>>>(g_qraw, g_kraw, g_vraw, g_Q, g_K, g_V);

    flash_attn<<<dim3(S_ / 64, B_ * H_), 256, sizeof(SmemAttn)>>>(g_Q, g_K, g_V, g_O);

    transpose_O<<<TOT_ / 256, 256>>>(g_O, g_Ot);

    gemm_f2<<<gg, 256>>>(g_Ot, Wo, out, M_, D_, D_);
}